// round 3
// baseline (speedup 1.0000x reference)
#include <cuda_runtime.h>
#include <cuda_bf16.h>
#include <cstdint>

// ---------------------------------------------------------------------------
// GatedExpertsEncoder: gating MLP (fp32 SIMT) + 3 soft-MoE layers as single
// big GEMMs (B x 4096) @ (4096 x 512), bf16x2 split precision (3 products,
// a0b0 + a0b1 + a1b0) with mma.sync.m16n8k16.bf16, fp32 accumulate.
// ---------------------------------------------------------------------------

static constexpr int BATCH = 65536;
static constexpr int DIN   = 512;
static constexpr int DH    = 512;
static constexpr int EXPN  = 8;
static constexpr int KTOT  = EXPN * DIN;   // 4096

// scratch (device globals: no allocation allowed)
__device__ float g_w [(size_t)BATCH * EXPN];
__device__ float g_h1[(size_t)BATCH * DH];
__device__ float g_h2[(size_t)BATCH * DH];

__device__ __forceinline__ float eluf(float x) { return x > 0.f ? x : expm1f(x); }

// pack {b16(vk1) : high, b16(vk) : low}
__device__ __forceinline__ uint32_t packbf2(float vk, float vk1) {
    uint32_t r;
    asm("cvt.rn.bf16x2.f32 %0, %1, %2;" : "=r"(r) : "f"(vk1), "f"(vk));
    return r;
}
// split a float pair into hi bf16x2 word + lo (residual) bf16x2 word
__device__ __forceinline__ void splitbf2(float vk, float vk1, uint32_t& hi, uint32_t& lo) {
    hi = packbf2(vk, vk1);
    float hk  = __uint_as_float(hi << 16);
    float hk1 = __uint_as_float(hi & 0xFFFF0000u);
    lo = packbf2(vk - hk, vk1 - hk1);
}

// ---------------------------------------------------------------------------
// Gating: warp-per-row fused 3-stage MLP. Weights (132 KB) are cache-resident.
// idx may be int32 (JAX x64 disabled) or int64; detect from arange pattern.
// ---------------------------------------------------------------------------
__global__ void gating_kernel(const float* __restrict__ z,
                              const void* __restrict__ idx_raw,
                              const float* __restrict__ Wg1, const float* __restrict__ bg1,
                              const float* __restrict__ Wg2, const float* __restrict__ bg2,
                              const float* __restrict__ Wg3, const float* __restrict__ bg3)
{
    __shared__ float bufA[8][128];
    __shared__ float bufB[8][128];
    const int warp = threadIdx.x >> 5;
    const int lane = threadIdx.x & 31;
    const int gwarp = blockIdx.x * 8 + warp;
    const int nwarp = gridDim.x * 8;

    const int* idx32 = (const int*)idx_raw;
    const bool is64 = (idx32[1] == 0);   // int64 arange: [0,0,1,0,...]

    for (int row = gwarp; row < BATCH; row += nwarp) {
        const float* zr = z + (size_t)row * DIN;
        for (int k = lane; k < 128; k += 32) {
            int col = is64 ? idx32[2 * k] : idx32[k];
            bufA[warp][k] = zr[col & (DIN - 1)];
        }
        __syncwarp();
        {
            float s0 = bg1[lane * 4 + 0], s1 = bg1[lane * 4 + 1];
            float s2 = bg1[lane * 4 + 2], s3 = bg1[lane * 4 + 3];
            #pragma unroll 8
            for (int k = 0; k < 128; ++k) {
                float xk = bufA[warp][k];
                float4 wv = *(const float4*)(Wg1 + k * 128 + lane * 4);
                s0 = fmaf(xk, wv.x, s0); s1 = fmaf(xk, wv.y, s1);
                s2 = fmaf(xk, wv.z, s2); s3 = fmaf(xk, wv.w, s3);
            }
            bufB[warp][lane * 4 + 0] = eluf(s0);
            bufB[warp][lane * 4 + 1] = eluf(s1);
            bufB[warp][lane * 4 + 2] = eluf(s2);
            bufB[warp][lane * 4 + 3] = eluf(s3);
        }
        __syncwarp();
        {
            float s0 = bg2[lane * 4 + 0], s1 = bg2[lane * 4 + 1];
            float s2 = bg2[lane * 4 + 2], s3 = bg2[lane * 4 + 3];
            #pragma unroll 8
            for (int k = 0; k < 128; ++k) {
                float xk = bufB[warp][k];
                float4 wv = *(const float4*)(Wg2 + k * 128 + lane * 4);
                s0 = fmaf(xk, wv.x, s0); s1 = fmaf(xk, wv.y, s1);
                s2 = fmaf(xk, wv.z, s2); s3 = fmaf(xk, wv.w, s3);
            }
            bufA[warp][lane * 4 + 0] = eluf(s0);
            bufA[warp][lane * 4 + 1] = eluf(s1);
            bufA[warp][lane * 4 + 2] = eluf(s2);
            bufA[warp][lane * 4 + 3] = eluf(s3);
        }
        __syncwarp();
        if (lane < 8) {
            float s = bg3[lane];
            #pragma unroll 8
            for (int k = 0; k < 128; ++k)
                s = fmaf(bufA[warp][k], Wg3[k * 8 + lane], s);
            g_w[(size_t)row * 8 + lane] = s;
        }
        __syncwarp();
    }
}

// ---------------------------------------------------------------------------
// Expert layer GEMM, bf16x2 split. CTA tile 128x128, BK=32, 8 warps (2x4),
// warp tile 64x32, m16n8k16 bf16. Smem holds hi/lo packed-bf16x2 tiles.
// ---------------------------------------------------------------------------
static constexpr int BM = 128, BN = 128, BK = 32;
static constexpr int ASTRW = 20;    // A smem row stride in uint32 words (16 data + 4 pad)
static constexpr int BSTRW = 136;   // B smem row stride in uint32 words
static constexpr int SM_AH = 2 * BM * ASTRW;         // 5120 words per (hi|lo)
static constexpr int SM_BH = 2 * (BK / 2) * BSTRW;   // 4352 words per (hi|lo)
static constexpr int SM_W    = BM * EXPN;            // 1024 floats
static constexpr int SM_BIAS = EXPN * BN;            // 1024 floats
static constexpr int SMEM_WORDS = 2 * SM_AH + 2 * SM_BH + SM_W + SM_BIAS;  // 20992
static constexpr int SMEM_BYTES = SMEM_WORDS * 4;                          // 83968 B

__device__ __forceinline__ void mma_bf16(float c[4], const uint32_t a[4], const uint32_t b[2]) {
    asm volatile(
        "mma.sync.aligned.m16n8k16.row.col.f32.bf16.bf16.f32 "
        "{%0,%1,%2,%3}, {%4,%5,%6,%7}, {%8,%9}, {%0,%1,%2,%3};\n"
        : "+f"(c[0]), "+f"(c[1]), "+f"(c[2]), "+f"(c[3])
        : "r"(a[0]), "r"(a[1]), "r"(a[2]), "r"(a[3]), "r"(b[0]), "r"(b[1]));
}

template <bool ACT, int MODE>
__global__ __launch_bounds__(256)
void layer_kernel(const float* __restrict__ Xp, const float* __restrict__ Wst,
                  const float* __restrict__ bias, float* __restrict__ Yp)
{
    const float* X = (MODE == 0) ? Xp : (MODE == 1 ? (const float*)g_h1 : (const float*)g_h2);
    float*       Y = (MODE == 0) ? (float*)g_h1 : (MODE == 1 ? (float*)g_h2 : Yp);

    extern __shared__ uint32_t smw[];
    uint32_t* Ah = smw;                 // [2][BM][ASTRW]
    uint32_t* Al = Ah + SM_AH;
    uint32_t* Bh = Al + SM_AH;          // [2][16][BSTRW]
    uint32_t* Bl = Bh + SM_BH;
    float*   wsm = (float*)(Bl + SM_BH);
    float*   bsm = wsm + SM_W;

    const int tid  = threadIdx.x;
    const int lane = tid & 31;
    const int warp = tid >> 5;
    const int g = lane >> 2, t = lane & 3;
    const int wm = warp >> 2, wn = warp & 3;     // 2 x 4 warp grid
    const int mBase = blockIdx.y * BM;
    const int nBase = blockIdx.x * BN;

    for (int i = tid; i < SM_W; i += 256)    wsm[i] = g_w[(size_t)mBase * EXPN + i];
    for (int i = tid; i < SM_BIAS; i += 256) bsm[i] = bias[(i >> 7) * DH + nBase + (i & 127)];
    __syncthreads();   // wsm used by A staging below

    float acc[4][4][4];
    #pragma unroll
    for (int mt = 0; mt < 4; ++mt)
        #pragma unroll
        for (int nf = 0; nf < 4; ++nf)
            #pragma unroll
            for (int q = 0; q < 4; ++q) acc[mt][nf][q] = 0.f;

    float4 avr[4];          // staged A (w-scaled): r = tid>>3, k = (tid&7)*4 ..
    float4 bvr[2][2];       // staged B: item u: rows 2p,2p+1, 4 n-cols

    auto ldgA = [&](int it) {
        const int e  = it >> 4;
        const int i0 = (it & 15) * BK;
        #pragma unroll
        for (int u = 0; u < 4; ++u) {
            int j = tid + 256 * u;
            int r = j >> 3, c4 = j & 7;
            float4 v = *(const float4*)(X + (size_t)(mBase + r) * DIN + i0 + c4 * 4);
            float s = wsm[r * 8 + e];
            v.x *= s; v.y *= s; v.z *= s; v.w *= s;
            avr[u] = v;
        }
    };
    auto ldgB = [&](int it) {
        const float* wbase = Wst + (size_t)it * BK * DH + nBase;
        #pragma unroll
        for (int u = 0; u < 2; ++u) {
            int j = tid + 256 * u;
            int p = j >> 5, n4 = j & 31;
            bvr[u][0] = *(const float4*)(wbase + (size_t)(2 * p)     * DH + n4 * 4);
            bvr[u][1] = *(const float4*)(wbase + (size_t)(2 * p + 1) * DH + n4 * 4);
        }
    };
    auto stsAB = [&](int buf) {
        uint32_t* ah = Ah + buf * BM * ASTRW;
        uint32_t* al = Al + buf * BM * ASTRW;
        #pragma unroll
        for (int u = 0; u < 4; ++u) {
            int j = tid + 256 * u;
            int r = j >> 3, c4 = j & 7;
            float4 v = avr[u];
            uint32_t h0, l0, h1, l1;
            splitbf2(v.x, v.y, h0, l0);
            splitbf2(v.z, v.w, h1, l1);
            *(uint2*)(ah + r * ASTRW + c4 * 2) = make_uint2(h0, h1);
            *(uint2*)(al + r * ASTRW + c4 * 2) = make_uint2(l0, l1);
        }
        uint32_t* bh = Bh + buf * (BK / 2) * BSTRW;
        uint32_t* bl = Bl + buf * (BK / 2) * BSTRW;
        #pragma unroll
        for (int u = 0; u < 2; ++u) {
            int j = tid + 256 * u;
            int p = j >> 5, n4 = j & 31;
            float4 r0 = bvr[u][0], r1 = bvr[u][1];
            uint32_t h[4], l[4];
            splitbf2(r0.x, r1.x, h[0], l[0]);
            splitbf2(r0.y, r1.y, h[1], l[1]);
            splitbf2(r0.z, r1.z, h[2], l[2]);
            splitbf2(r0.w, r1.w, h[3], l[3]);
            *(uint4*)(bh + p * BSTRW + n4 * 4) = make_uint4(h[0], h[1], h[2], h[3]);
            *(uint4*)(bl + p * BSTRW + n4 * 4) = make_uint4(l[0], l[1], l[2], l[3]);
        }
    };

    // prologue: chunk 0
    ldgA(0); ldgB(0);
    stsAB(0);
    __syncthreads();

    const int NIT = KTOT / BK;   // 128
    for (int it = 0; it < NIT; ++it) {
        const int cur = it & 1, nxt = cur ^ 1;
        const bool more = (it + 1) < NIT;
        if (more) { ldgA(it + 1); ldgB(it + 1); }

        const uint32_t* ah = Ah + cur * BM * ASTRW;
        const uint32_t* al = Al + cur * BM * ASTRW;
        const uint32_t* bh = Bh + cur * (BK / 2) * BSTRW;
        const uint32_t* bl = Bl + cur * (BK / 2) * BSTRW;

        #pragma unroll
        for (int ks = 0; ks < 2; ++ks) {   // two k16 steps per BK=32 chunk
            uint32_t afh[4][4], afl[4][4], bfh[4][2], bfl[4][2];
            #pragma unroll
            for (int mt = 0; mt < 4; ++mt) {
                const int r0 = (wm * 64 + mt * 16 + g) * ASTRW + ks * 8 + t;
                const int r1 = r0 + 8 * ASTRW;
                afh[mt][0] = ah[r0];     afh[mt][1] = ah[r1];
                afh[mt][2] = ah[r0 + 4]; afh[mt][3] = ah[r1 + 4];
                afl[mt][0] = al[r0];     afl[mt][1] = al[r1];
                afl[mt][2] = al[r0 + 4]; afl[mt][3] = al[r1 + 4];
            }
            #pragma unroll
            for (int nf = 0; nf < 4; ++nf) {
                const int n = wn * 32 + nf * 8 + g;
                const int p0 = (ks * 8 + t) * BSTRW + n;
                bfh[nf][0] = bh[p0]; bfh[nf][1] = bh[p0 + 4 * BSTRW];
                bfl[nf][0] = bl[p0]; bfl[nf][1] = bl[p0 + 4 * BSTRW];
            }
            #pragma unroll
            for (int mt = 0; mt < 4; ++mt)
                #pragma unroll
                for (int nf = 0; nf < 4; ++nf) {
                    mma_bf16(acc[mt][nf], afh[mt], bfh[nf]);   // a0*b0
                    mma_bf16(acc[mt][nf], afh[mt], bfl[nf]);   // a0*b1
                    mma_bf16(acc[mt][nf], afl[mt], bfh[nf]);   // a1*b0
                }
        }
        if (more) {
            stsAB(nxt);
            __syncthreads();
        }
    }

    // epilogue: + w @ bias, activation, store
    #pragma unroll
    for (int mt = 0; mt < 4; ++mt) {
        const int r0 = wm * 64 + mt * 16 + g;
        float w0[8], w1[8];
        #pragma unroll
        for (int e = 0; e < 8; ++e) {
            w0[e] = wsm[r0 * 8 + e];
            w1[e] = wsm[(r0 + 8) * 8 + e];
        }
        #pragma unroll
        for (int nf = 0; nf < 4; ++nf) {
            const int c = wn * 32 + nf * 8 + t * 2;
            float b00 = 0.f, b01 = 0.f, b10 = 0.f, b11 = 0.f;
            #pragma unroll
            for (int e = 0; e < 8; ++e) {
                float be0 = bsm[e * 128 + c], be1 = bsm[e * 128 + c + 1];
                b00 = fmaf(w0[e], be0, b00); b01 = fmaf(w0[e], be1, b01);
                b10 = fmaf(w1[e], be0, b10); b11 = fmaf(w1[e], be1, b11);
            }
            float v0 = acc[mt][nf][0] + b00;
            float v1 = acc[mt][nf][1] + b01;
            float v2 = acc[mt][nf][2] + b10;
            float v3 = acc[mt][nf][3] + b11;
            if (ACT) { v0 = eluf(v0); v1 = eluf(v1); v2 = eluf(v2); v3 = eluf(v3); }
            *(float2*)(Y + (size_t)(mBase + r0)     * DH + nBase + c) = make_float2(v0, v1);
            *(float2*)(Y + (size_t)(mBase + r0 + 8) * DH + nBase + c) = make_float2(v2, v3);
        }
    }
}

// ---------------------------------------------------------------------------
extern "C" void kernel_launch(void* const* d_in, const int* in_sizes, int n_in,
                              void* d_out, int out_size)
{
    const float* z   = (const float*)d_in[0];
    const void*  idx = (const void*)d_in[1];
    const float* Wg1 = (const float*)d_in[2];
    const float* bg1 = (const float*)d_in[3];
    const float* Wg2 = (const float*)d_in[4];
    const float* bg2 = (const float*)d_in[5];
    const float* Wg3 = (const float*)d_in[6];
    const float* bg3 = (const float*)d_in[7];
    const float* W1  = (const float*)d_in[8];
    const float* b1  = (const float*)d_in[9];
    const float* W2  = (const float*)d_in[10];
    const float* b2  = (const float*)d_in[11];
    const float* W3  = (const float*)d_in[12];
    const float* b3  = (const float*)d_in[13];
    float* out = (float*)d_out;

    cudaFuncSetAttribute(layer_kernel<true , 0>, cudaFuncAttributeMaxDynamicSharedMemorySize, SMEM_BYTES);
    cudaFuncSetAttribute(layer_kernel<true , 1>, cudaFuncAttributeMaxDynamicSharedMemorySize, SMEM_BYTES);
    cudaFuncSetAttribute(layer_kernel<false, 2>, cudaFuncAttributeMaxDynamicSharedMemorySize, SMEM_BYTES);

    gating_kernel<<<1024, 256>>>(z, idx, Wg1, bg1, Wg2, bg2, Wg3, bg3);

    dim3 grid(DH / BN, BATCH / BM);   // (4, 512)
    layer_kernel<true , 0><<<grid, 256, SMEM_BYTES>>>(z,       W1, b1, nullptr);
    layer_kernel<true , 1><<<grid, 256, SMEM_BYTES>>>(nullptr, W2, b2, nullptr);
    layer_kernel<false, 2><<<grid, 256, SMEM_BYTES>>>(nullptr, W3, b3, out);
}

// round 4
// speedup vs baseline: 1.0005x; 1.0005x over previous
#include <cuda_runtime.h>
#include <cuda_bf16.h>
#include <cstdint>

// ---------------------------------------------------------------------------
// GatedExpertsEncoder: gating MLP (fp32 SIMT) + 3 soft-MoE layers as single
// big GEMMs (B x 4096) @ (4096 x 512), bf16x2 split precision (3 products,
// a0b0 + a0b1 + a1b0) with mma.sync.m16n8k16.bf16, fp32 accumulate.
// ---------------------------------------------------------------------------

static constexpr int BATCH = 65536;
static constexpr int DIN   = 512;
static constexpr int DH    = 512;
static constexpr int EXPN  = 8;
static constexpr int KTOT  = EXPN * DIN;   // 4096

// scratch (device globals: no allocation allowed)
__device__ float g_w [(size_t)BATCH * EXPN];
__device__ float g_h1[(size_t)BATCH * DH];
__device__ float g_h2[(size_t)BATCH * DH];

__device__ __forceinline__ float eluf(float x) { return x > 0.f ? x : expm1f(x); }

// pack {b16(vk1) : high, b16(vk) : low}
__device__ __forceinline__ uint32_t packbf2(float vk, float vk1) {
    uint32_t r;
    asm("cvt.rn.bf16x2.f32 %0, %1, %2;" : "=r"(r) : "f"(vk1), "f"(vk));
    return r;
}
// split a float pair into hi bf16x2 word + lo (residual) bf16x2 word
__device__ __forceinline__ void splitbf2(float vk, float vk1, uint32_t& hi, uint32_t& lo) {
    hi = packbf2(vk, vk1);
    float hk  = __uint_as_float(hi << 16);
    float hk1 = __uint_as_float(hi & 0xFFFF0000u);
    lo = packbf2(vk - hk, vk1 - hk1);
}

// ---------------------------------------------------------------------------
// Gating: warp-per-row fused 3-stage MLP. Weights (132 KB) are cache-resident.
// idx may be int32 (JAX x64 disabled) or int64; detect from arange pattern.
// ---------------------------------------------------------------------------
__global__ void gating_kernel(const float* __restrict__ z,
                              const void* __restrict__ idx_raw,
                              const float* __restrict__ Wg1, const float* __restrict__ bg1,
                              const float* __restrict__ Wg2, const float* __restrict__ bg2,
                              const float* __restrict__ Wg3, const float* __restrict__ bg3)
{
    __shared__ float bufA[8][128];
    __shared__ float bufB[8][128];
    const int warp = threadIdx.x >> 5;
    const int lane = threadIdx.x & 31;
    const int gwarp = blockIdx.x * 8 + warp;
    const int nwarp = gridDim.x * 8;

    const int* idx32 = (const int*)idx_raw;
    const bool is64 = (idx32[1] == 0);   // int64 arange: [0,0,1,0,...]

    for (int row = gwarp; row < BATCH; row += nwarp) {
        const float* zr = z + (size_t)row * DIN;
        for (int k = lane; k < 128; k += 32) {
            int col = is64 ? idx32[2 * k] : idx32[k];
            bufA[warp][k] = zr[col & (DIN - 1)];
        }
        __syncwarp();
        {
            float s0 = bg1[lane * 4 + 0], s1 = bg1[lane * 4 + 1];
            float s2 = bg1[lane * 4 + 2], s3 = bg1[lane * 4 + 3];
            #pragma unroll 8
            for (int k = 0; k < 128; ++k) {
                float xk = bufA[warp][k];
                float4 wv = *(const float4*)(Wg1 + k * 128 + lane * 4);
                s0 = fmaf(xk, wv.x, s0); s1 = fmaf(xk, wv.y, s1);
                s2 = fmaf(xk, wv.z, s2); s3 = fmaf(xk, wv.w, s3);
            }
            bufB[warp][lane * 4 + 0] = eluf(s0);
            bufB[warp][lane * 4 + 1] = eluf(s1);
            bufB[warp][lane * 4 + 2] = eluf(s2);
            bufB[warp][lane * 4 + 3] = eluf(s3);
        }
        __syncwarp();
        {
            float s0 = bg2[lane * 4 + 0], s1 = bg2[lane * 4 + 1];
            float s2 = bg2[lane * 4 + 2], s3 = bg2[lane * 4 + 3];
            #pragma unroll 8
            for (int k = 0; k < 128; ++k) {
                float xk = bufB[warp][k];
                float4 wv = *(const float4*)(Wg2 + k * 128 + lane * 4);
                s0 = fmaf(xk, wv.x, s0); s1 = fmaf(xk, wv.y, s1);
                s2 = fmaf(xk, wv.z, s2); s3 = fmaf(xk, wv.w, s3);
            }
            bufA[warp][lane * 4 + 0] = eluf(s0);
            bufA[warp][lane * 4 + 1] = eluf(s1);
            bufA[warp][lane * 4 + 2] = eluf(s2);
            bufA[warp][lane * 4 + 3] = eluf(s3);
        }
        __syncwarp();
        if (lane < 8) {
            float s = bg3[lane];
            #pragma unroll 8
            for (int k = 0; k < 128; ++k)
                s = fmaf(bufA[warp][k], Wg3[k * 8 + lane], s);
            g_w[(size_t)row * 8 + lane] = s;
        }
        __syncwarp();
    }
}

// ---------------------------------------------------------------------------
// Expert layer GEMM, bf16x2 split. CTA tile 128x128, BK=32, 8 warps (2x4),
// warp tile 64x32, m16n8k16 bf16. Smem holds hi/lo packed-bf16x2 tiles.
// ---------------------------------------------------------------------------
static constexpr int BM = 128, BN = 128, BK = 32;
static constexpr int ASTRW = 20;    // A smem row stride in uint32 words (16 data + 4 pad)
static constexpr int BSTRW = 136;   // B smem row stride in uint32 words
static constexpr int SM_AH = 2 * BM * ASTRW;         // 5120 words per (hi|lo)
static constexpr int SM_BH = 2 * (BK / 2) * BSTRW;   // 4352 words per (hi|lo)
static constexpr int SM_W    = BM * EXPN;            // 1024 floats
static constexpr int SM_BIAS = EXPN * BN;            // 1024 floats
static constexpr int SMEM_WORDS = 2 * SM_AH + 2 * SM_BH + SM_W + SM_BIAS;  // 20992
static constexpr int SMEM_BYTES = SMEM_WORDS * 4;                          // 83968 B

__device__ __forceinline__ void mma_bf16(float c[4], const uint32_t a[4], const uint32_t b[2]) {
    asm volatile(
        "mma.sync.aligned.m16n8k16.row.col.f32.bf16.bf16.f32 "
        "{%0,%1,%2,%3}, {%4,%5,%6,%7}, {%8,%9}, {%0,%1,%2,%3};\n"
        : "+f"(c[0]), "+f"(c[1]), "+f"(c[2]), "+f"(c[3])
        : "r"(a[0]), "r"(a[1]), "r"(a[2]), "r"(a[3]), "r"(b[0]), "r"(b[1]));
}

template <bool ACT, int MODE>
__global__ __launch_bounds__(256)
void layer_kernel(const float* __restrict__ Xp, const float* __restrict__ Wst,
                  const float* __restrict__ bias, float* __restrict__ Yp)
{
    const float* X = (MODE == 0) ? Xp : (MODE == 1 ? (const float*)g_h1 : (const float*)g_h2);
    float*       Y = (MODE == 0) ? (float*)g_h1 : (MODE == 1 ? (float*)g_h2 : Yp);

    extern __shared__ uint32_t smw[];
    uint32_t* Ah = smw;                 // [2][BM][ASTRW]
    uint32_t* Al = Ah + SM_AH;
    uint32_t* Bh = Al + SM_AH;          // [2][16][BSTRW]
    uint32_t* Bl = Bh + SM_BH;
    float*   wsm = (float*)(Bl + SM_BH);
    float*   bsm = wsm + SM_W;

    const int tid  = threadIdx.x;
    const int lane = tid & 31;
    const int warp = tid >> 5;
    const int g = lane >> 2, t = lane & 3;
    const int wm = warp >> 2, wn = warp & 3;     // 2 x 4 warp grid
    const int mBase = blockIdx.y * BM;
    const int nBase = blockIdx.x * BN;

    for (int i = tid; i < SM_W; i += 256)    wsm[i] = g_w[(size_t)mBase * EXPN + i];
    for (int i = tid; i < SM_BIAS; i += 256) bsm[i] = bias[(i >> 7) * DH + nBase + (i & 127)];
    __syncthreads();   // wsm used by A staging below

    float acc[4][4][4];
    #pragma unroll
    for (int mt = 0; mt < 4; ++mt)
        #pragma unroll
        for (int nf = 0; nf < 4; ++nf)
            #pragma unroll
            for (int q = 0; q < 4; ++q) acc[mt][nf][q] = 0.f;

    float4 avr[4];          // staged A (w-scaled): r = tid>>3, k = (tid&7)*4 ..
    float4 bvr[2][2];       // staged B: item u: rows 2p,2p+1, 4 n-cols

    auto ldgA = [&](int it) {
        const int e  = it >> 4;
        const int i0 = (it & 15) * BK;
        #pragma unroll
        for (int u = 0; u < 4; ++u) {
            int j = tid + 256 * u;
            int r = j >> 3, c4 = j & 7;
            float4 v = *(const float4*)(X + (size_t)(mBase + r) * DIN + i0 + c4 * 4);
            float s = wsm[r * 8 + e];
            v.x *= s; v.y *= s; v.z *= s; v.w *= s;
            avr[u] = v;
        }
    };
    auto ldgB = [&](int it) {
        const float* wbase = Wst + (size_t)it * BK * DH + nBase;
        #pragma unroll
        for (int u = 0; u < 2; ++u) {
            int j = tid + 256 * u;
            int p = j >> 5, n4 = j & 31;
            bvr[u][0] = *(const float4*)(wbase + (size_t)(2 * p)     * DH + n4 * 4);
            bvr[u][1] = *(const float4*)(wbase + (size_t)(2 * p + 1) * DH + n4 * 4);
        }
    };
    auto stsAB = [&](int buf) {
        uint32_t* ah = Ah + buf * BM * ASTRW;
        uint32_t* al = Al + buf * BM * ASTRW;
        #pragma unroll
        for (int u = 0; u < 4; ++u) {
            int j = tid + 256 * u;
            int r = j >> 3, c4 = j & 7;
            float4 v = avr[u];
            uint32_t h0, l0, h1, l1;
            splitbf2(v.x, v.y, h0, l0);
            splitbf2(v.z, v.w, h1, l1);
            *(uint2*)(ah + r * ASTRW + c4 * 2) = make_uint2(h0, h1);
            *(uint2*)(al + r * ASTRW + c4 * 2) = make_uint2(l0, l1);
        }
        uint32_t* bh = Bh + buf * (BK / 2) * BSTRW;
        uint32_t* bl = Bl + buf * (BK / 2) * BSTRW;
        #pragma unroll
        for (int u = 0; u < 2; ++u) {
            int j = tid + 256 * u;
            int p = j >> 5, n4 = j & 31;
            float4 r0 = bvr[u][0], r1 = bvr[u][1];
            uint32_t h[4], l[4];
            splitbf2(r0.x, r1.x, h[0], l[0]);
            splitbf2(r0.y, r1.y, h[1], l[1]);
            splitbf2(r0.z, r1.z, h[2], l[2]);
            splitbf2(r0.w, r1.w, h[3], l[3]);
            *(uint4*)(bh + p * BSTRW + n4 * 4) = make_uint4(h[0], h[1], h[2], h[3]);
            *(uint4*)(bl + p * BSTRW + n4 * 4) = make_uint4(l[0], l[1], l[2], l[3]);
        }
    };

    // prologue: chunk 0
    ldgA(0); ldgB(0);
    stsAB(0);
    __syncthreads();

    const int NIT = KTOT / BK;   // 128
    for (int it = 0; it < NIT; ++it) {
        const int cur = it & 1, nxt = cur ^ 1;
        const bool more = (it + 1) < NIT;
        if (more) { ldgA(it + 1); ldgB(it + 1); }

        const uint32_t* ah = Ah + cur * BM * ASTRW;
        const uint32_t* al = Al + cur * BM * ASTRW;
        const uint32_t* bh = Bh + cur * (BK / 2) * BSTRW;
        const uint32_t* bl = Bl + cur * (BK / 2) * BSTRW;

        #pragma unroll
        for (int ks = 0; ks < 2; ++ks) {   // two k16 steps per BK=32 chunk
            uint32_t afh[4][4], afl[4][4], bfh[4][2], bfl[4][2];
            #pragma unroll
            for (int mt = 0; mt < 4; ++mt) {
                const int r0 = (wm * 64 + mt * 16 + g) * ASTRW + ks * 8 + t;
                const int r1 = r0 + 8 * ASTRW;
                afh[mt][0] = ah[r0];     afh[mt][1] = ah[r1];
                afh[mt][2] = ah[r0 + 4]; afh[mt][3] = ah[r1 + 4];
                afl[mt][0] = al[r0];     afl[mt][1] = al[r1];
                afl[mt][2] = al[r0 + 4]; afl[mt][3] = al[r1 + 4];
            }
            #pragma unroll
            for (int nf = 0; nf < 4; ++nf) {
                const int n = wn * 32 + nf * 8 + g;
                const int p0 = (ks * 8 + t) * BSTRW + n;
                bfh[nf][0] = bh[p0]; bfh[nf][1] = bh[p0 + 4 * BSTRW];
                bfl[nf][0] = bl[p0]; bfl[nf][1] = bl[p0 + 4 * BSTRW];
            }
            #pragma unroll
            for (int mt = 0; mt < 4; ++mt)
                #pragma unroll
                for (int nf = 0; nf < 4; ++nf) {
                    mma_bf16(acc[mt][nf], afh[mt], bfh[nf]);   // a0*b0
                    mma_bf16(acc[mt][nf], afh[mt], bfl[nf]);   // a0*b1
                    mma_bf16(acc[mt][nf], afl[mt], bfh[nf]);   // a1*b0
                }
        }
        if (more) {
            stsAB(nxt);
            __syncthreads();
        }
    }

    // epilogue: + w @ bias, activation, store
    #pragma unroll
    for (int mt = 0; mt < 4; ++mt) {
        const int r0 = wm * 64 + mt * 16 + g;
        float w0[8], w1[8];
        #pragma unroll
        for (int e = 0; e < 8; ++e) {
            w0[e] = wsm[r0 * 8 + e];
            w1[e] = wsm[(r0 + 8) * 8 + e];
        }
        #pragma unroll
        for (int nf = 0; nf < 4; ++nf) {
            const int c = wn * 32 + nf * 8 + t * 2;
            float b00 = 0.f, b01 = 0.f, b10 = 0.f, b11 = 0.f;
            #pragma unroll
            for (int e = 0; e < 8; ++e) {
                float be0 = bsm[e * 128 + c], be1 = bsm[e * 128 + c + 1];
                b00 = fmaf(w0[e], be0, b00); b01 = fmaf(w0[e], be1, b01);
                b10 = fmaf(w1[e], be0, b10); b11 = fmaf(w1[e], be1, b11);
            }
            float v0 = acc[mt][nf][0] + b00;
            float v1 = acc[mt][nf][1] + b01;
            float v2 = acc[mt][nf][2] + b10;
            float v3 = acc[mt][nf][3] + b11;
            if (ACT) { v0 = eluf(v0); v1 = eluf(v1); v2 = eluf(v2); v3 = eluf(v3); }
            *(float2*)(Y + (size_t)(mBase + r0)     * DH + nBase + c) = make_float2(v0, v1);
            *(float2*)(Y + (size_t)(mBase + r0 + 8) * DH + nBase + c) = make_float2(v2, v3);
        }
    }
}

// ---------------------------------------------------------------------------
extern "C" void kernel_launch(void* const* d_in, const int* in_sizes, int n_in,
                              void* d_out, int out_size)
{
    const float* z   = (const float*)d_in[0];
    const void*  idx = (const void*)d_in[1];
    const float* Wg1 = (const float*)d_in[2];
    const float* bg1 = (const float*)d_in[3];
    const float* Wg2 = (const float*)d_in[4];
    const float* bg2 = (const float*)d_in[5];
    const float* Wg3 = (const float*)d_in[6];
    const float* bg3 = (const float*)d_in[7];
    const float* W1  = (const float*)d_in[8];
    const float* b1  = (const float*)d_in[9];
    const float* W2  = (const float*)d_in[10];
    const float* b2  = (const float*)d_in[11];
    const float* W3  = (const float*)d_in[12];
    const float* b3  = (const float*)d_in[13];
    float* out = (float*)d_out;

    cudaFuncSetAttribute(layer_kernel<true , 0>, cudaFuncAttributeMaxDynamicSharedMemorySize, SMEM_BYTES);
    cudaFuncSetAttribute(layer_kernel<true , 1>, cudaFuncAttributeMaxDynamicSharedMemorySize, SMEM_BYTES);
    cudaFuncSetAttribute(layer_kernel<false, 2>, cudaFuncAttributeMaxDynamicSharedMemorySize, SMEM_BYTES);

    gating_kernel<<<1024, 256>>>(z, idx, Wg1, bg1, Wg2, bg2, Wg3, bg3);

    dim3 grid(DH / BN, BATCH / BM);   // (4, 512)
    layer_kernel<true , 0><<<grid, 256, SMEM_BYTES>>>(z,       W1, b1, nullptr);
    layer_kernel<true , 1><<<grid, 256, SMEM_BYTES>>>(nullptr, W2, b2, nullptr);
    layer_kernel<false, 2><<<grid, 256, SMEM_BYTES>>>(nullptr, W3, b3, out);
}

// round 6
// speedup vs baseline: 1.2572x; 1.2565x over previous
#include <cuda_runtime.h>
#include <cuda_bf16.h>
#include <cstdint>

// ---------------------------------------------------------------------------
// GatedExpertsEncoder (sm_103a via legacy mma.sync path; tcgen05 unavailable
// in this toolchain: harness compiles through compute_103 PTX).
// out = sum_e w[:,e] * act(X @ W_e + b_e), 3 layers, E=8 soft MoE.
// Single GEMM per layer: A'[b, e*512+i] = w[b,e]*x[b,i], (B x 4096)@(4096 x 512)
// bf16 split precision: ah*bh + ah*bl + al*bh, fp32 accumulate (m16n8k16).
// W pre-transposed+split once per launch into bf16 hi/lo [DH][4096].
// ldmatrix fragment feeding + cp.async B staging + 2 CTAs/SM.
// ---------------------------------------------------------------------------

static constexpr int BATCH = 65536;
static constexpr int DIN   = 512;
static constexpr int DH    = 512;
static constexpr int EXPN  = 8;
static constexpr int KTOT  = EXPN * DIN;   // 4096

static constexpr int BM = 128, BN = 128, BK = 32;
static constexpr int NIT = KTOT / BK;      // 128

// smem: row stride 40 bf16 (80 B) -> LDSM 8-row pointer sets hit 8 distinct
// 4-bank groups; STS/cp.async also conflict-free.
static constexpr int RSTRB = 80;                   // bytes per smem row
static constexpr int TILEB = 128 * RSTRB;          // 10240 B per tile
static constexpr int OFF_AL = TILEB;               // A lo
static constexpr int OFF_BH = 2 * TILEB;           // B hi
static constexpr int OFF_BL = 3 * TILEB;           // B lo
static constexpr int STAGE  = 4 * TILEB;           // 40960 B
static constexpr int WSM_OFF = 2 * STAGE;          // 81920, 128*8 fp32 = 4 KB
static constexpr int BSM_OFF = WSM_OFF + 4096;     // 86016, 8*128 fp32 = 4 KB
static constexpr int SMEM_BYTES = BSM_OFF + 4096;  // 90112 B (2 CTAs fit in 228 KB)

// ------------------------------ scratch -----------------------------------
__device__ __align__(16) float g_w [(size_t)BATCH * EXPN];
__device__ __align__(16) float g_h1[(size_t)BATCH * DH];
__device__ __align__(16) float g_h2[(size_t)BATCH * DH];
__device__ __align__(16) __nv_bfloat16 g_wth[(size_t)3 * DH * KTOT];
__device__ __align__(16) __nv_bfloat16 g_wtl[(size_t)3 * DH * KTOT];

// ------------------------------ helpers -----------------------------------
__device__ __forceinline__ float eluf(float x) { return x > 0.f ? x : expm1f(x); }

__device__ __forceinline__ uint32_t packbf2(float vlo, float vhi) {
    uint32_t r;
    asm("cvt.rn.bf16x2.f32 %0, %1, %2;" : "=r"(r) : "f"(vhi), "f"(vlo));
    return r;
}
__device__ __forceinline__ void splitbf2(float v0, float v1, uint32_t& hi, uint32_t& lo) {
    hi = packbf2(v0, v1);
    float h0 = __uint_as_float(hi << 16);
    float h1 = __uint_as_float(hi & 0xFFFF0000u);
    lo = packbf2(v0 - h0, v1 - h1);
}
__device__ __forceinline__ uint32_t smem_u32(const void* p) {
    uint32_t a;
    asm("{ .reg .u64 t; cvta.to.shared.u64 t, %1; cvt.u32.u64 %0, t; }" : "=r"(a) : "l"(p));
    return a;
}
__device__ __forceinline__ void sts64(uint32_t a, uint32_t x, uint32_t y) {
    asm volatile("st.shared.v2.b32 [%0], {%1,%2};" :: "r"(a), "r"(x), "r"(y) : "memory");
}
__device__ __forceinline__ void cp16(uint32_t dst, const void* src) {
    asm volatile("cp.async.cg.shared.global [%0], [%1], 16;" :: "r"(dst), "l"(src) : "memory");
}
__device__ __forceinline__ void ldsm4(uint32_t r[4], uint32_t addr) {
    asm volatile("ldmatrix.sync.aligned.m8n8.x4.shared.b16 {%0,%1,%2,%3}, [%4];"
                 : "=r"(r[0]), "=r"(r[1]), "=r"(r[2]), "=r"(r[3]) : "r"(addr));
}
__device__ __forceinline__ void mma_bf16(float c[4], const uint32_t a[4], const uint32_t b[2]) {
    asm volatile(
        "mma.sync.aligned.m16n8k16.row.col.f32.bf16.bf16.f32 "
        "{%0,%1,%2,%3}, {%4,%5,%6,%7}, {%8,%9}, {%0,%1,%2,%3};\n"
        : "+f"(c[0]), "+f"(c[1]), "+f"(c[2]), "+f"(c[3])
        : "r"(a[0]), "r"(a[1]), "r"(a[2]), "r"(a[3]), "r"(b[0]), "r"(b[1]));
}

// ---------------------------------------------------------------------------
// Gating MLP (proven in R3).
// ---------------------------------------------------------------------------
__global__ void gating_kernel(const float* __restrict__ z,
                              const void* __restrict__ idx_raw,
                              const float* __restrict__ Wg1, const float* __restrict__ bg1,
                              const float* __restrict__ Wg2, const float* __restrict__ bg2,
                              const float* __restrict__ Wg3, const float* __restrict__ bg3)
{
    __shared__ float bufA[8][128];
    __shared__ float bufB[8][128];
    const int warp = threadIdx.x >> 5;
    const int lane = threadIdx.x & 31;
    const int gwarp = blockIdx.x * 8 + warp;
    const int nwarp = gridDim.x * 8;

    const int* idx32 = (const int*)idx_raw;
    const bool is64 = (idx32[1] == 0);

    for (int row = gwarp; row < BATCH; row += nwarp) {
        const float* zr = z + (size_t)row * DIN;
        for (int k = lane; k < 128; k += 32) {
            int col = is64 ? idx32[2 * k] : idx32[k];
            bufA[warp][k] = zr[col & (DIN - 1)];
        }
        __syncwarp();
        {
            float s0 = bg1[lane * 4 + 0], s1 = bg1[lane * 4 + 1];
            float s2 = bg1[lane * 4 + 2], s3 = bg1[lane * 4 + 3];
            #pragma unroll 8
            for (int k = 0; k < 128; ++k) {
                float xk = bufA[warp][k];
                float4 wv = *(const float4*)(Wg1 + k * 128 + lane * 4);
                s0 = fmaf(xk, wv.x, s0); s1 = fmaf(xk, wv.y, s1);
                s2 = fmaf(xk, wv.z, s2); s3 = fmaf(xk, wv.w, s3);
            }
            bufB[warp][lane * 4 + 0] = eluf(s0);
            bufB[warp][lane * 4 + 1] = eluf(s1);
            bufB[warp][lane * 4 + 2] = eluf(s2);
            bufB[warp][lane * 4 + 3] = eluf(s3);
        }
        __syncwarp();
        {
            float s0 = bg2[lane * 4 + 0], s1 = bg2[lane * 4 + 1];
            float s2 = bg2[lane * 4 + 2], s3 = bg2[lane * 4 + 3];
            #pragma unroll 8
            for (int k = 0; k < 128; ++k) {
                float xk = bufB[warp][k];
                float4 wv = *(const float4*)(Wg2 + k * 128 + lane * 4);
                s0 = fmaf(xk, wv.x, s0); s1 = fmaf(xk, wv.y, s1);
                s2 = fmaf(xk, wv.z, s2); s3 = fmaf(xk, wv.w, s3);
            }
            bufA[warp][lane * 4 + 0] = eluf(s0);
            bufA[warp][lane * 4 + 1] = eluf(s1);
            bufA[warp][lane * 4 + 2] = eluf(s2);
            bufA[warp][lane * 4 + 3] = eluf(s3);
        }
        __syncwarp();
        if (lane < 8) {
            float s = bg3[lane];
            #pragma unroll 8
            for (int k = 0; k < 128; ++k)
                s = fmaf(bufA[warp][k], Wg3[k * 8 + lane], s);
            g_w[(size_t)row * 8 + lane] = s;
        }
        __syncwarp();
    }
}

// ---------------------------------------------------------------------------
// W pre-transpose+split: W[k=4096][o=512] fp32 -> Wt hi/lo [o=512][k=4096] bf16
// ---------------------------------------------------------------------------
__global__ void wsplit_kernel(const float* __restrict__ W, int layer)
{
    __shared__ float T[32][33];
    __nv_bfloat16* oh = g_wth + (size_t)layer * DH * KTOT;
    __nv_bfloat16* ol = g_wtl + (size_t)layer * DH * KTOT;
    const int kt = blockIdx.x * 32, ot = blockIdx.y * 32;
    const int tx = threadIdx.x, ty = threadIdx.y;   // 32 x 8
    #pragma unroll
    for (int i = 0; i < 4; ++i)
        T[ty + 8 * i][tx] = W[(size_t)(kt + ty + 8 * i) * DH + ot + tx];
    __syncthreads();
    #pragma unroll
    for (int i = 0; i < 4; ++i) {
        const int o = ot + ty + 8 * i, k = kt + tx;
        float v = T[tx][ty + 8 * i];
        __nv_bfloat16 h = __float2bfloat16(v);
        oh[(size_t)o * KTOT + k] = h;
        ol[(size_t)o * KTOT + k] = __float2bfloat16(v - __bfloat162float(h));
    }
}

// ---------------------------------------------------------------------------
// Layer kernel: CTA 128x128, 256 threads (8 warps, 4m x 2n, warp tile 32x64),
// 2 CTAs/SM. BK=32 double-buffered; A: LDG+scale+split+STS, B: cp.async of
// pre-split bf16; fragments via ldmatrix.x4.
// ---------------------------------------------------------------------------
template <bool ACT, int MODE>
__global__ __launch_bounds__(256, 2)
void layer_mm(const float* __restrict__ Xp, const float* __restrict__ bias,
              float* __restrict__ Yp)
{
    const float* X = (MODE == 0) ? Xp : (MODE == 1 ? (const float*)g_h1 : (const float*)g_h2);
    float*       Y = (MODE == 0) ? (float*)g_h1 : (MODE == 1 ? (float*)g_h2 : Yp);
    const __nv_bfloat16* Wth = g_wth + (size_t)MODE * DH * KTOT;
    const __nv_bfloat16* Wtl = g_wtl + (size_t)MODE * DH * KTOT;

    extern __shared__ char sm[];
    const uint32_t sb = smem_u32(sm);
    float* wsm = (float*)(sm + WSM_OFF);
    float* bsm = (float*)(sm + BSM_OFF);

    const int tid  = threadIdx.x;
    const int lane = tid & 31;
    const int warp = tid >> 5;
    const int g = lane >> 2, t = lane & 3;
    const int wm = warp >> 1, wn = warp & 1;        // 4 x 2 warps
    const int mBase = blockIdx.y * BM;
    const int nBase = blockIdx.x * BN;

    for (int i = tid; i < BM * EXPN; i += 256) wsm[i] = g_w[(size_t)mBase * EXPN + i];
    for (int i = tid; i < EXPN * BN; i += 256) bsm[i] = bias[(i >> 7) * DH + nBase + (i & 127)];
    __syncthreads();

    float acc[2][8][4];
    #pragma unroll
    for (int mt = 0; mt < 2; ++mt)
        #pragma unroll
        for (int nf = 0; nf < 8; ++nf)
            #pragma unroll
            for (int q = 0; q < 4; ++q) acc[mt][nf][q] = 0.f;

    float4 avr[4];

    // per-thread ldmatrix source addresses (stage-relative byte offsets)
    const uint32_t a_row = (uint32_t)(wm * 32 + (lane & 15));
    const uint32_t a_off = a_row * RSTRB + ((lane >> 4) & 1) * 16;
    const uint32_t b_row = (uint32_t)(wn * 64 + (lane & 7) + ((lane & 16) >> 1));
    const uint32_t b_off = b_row * RSTRB + ((lane >> 3) & 1) * 16;

    auto ldgA = [&](int it) {
        const int e  = it >> 4;
        const int i0 = (it & 15) * BK;
        #pragma unroll
        for (int u = 0; u < 4; ++u) {
            int j = tid + 256 * u;
            int r = j >> 3, c = j & 7;
            float4 v = *(const float4*)(X + (size_t)(mBase + r) * DIN + i0 + c * 4);
            float s = wsm[r * 8 + e];
            v.x *= s; v.y *= s; v.z *= s; v.w *= s;
            avr[u] = v;
        }
    };
    auto cpB = [&](int it, int buf) {
        const uint32_t base = sb + buf * STAGE;
        const size_t ko = (size_t)it * BK;
        #pragma unroll
        for (int u = 0; u < 2; ++u) {
            int j = tid + 256 * u;
            int n = j >> 2, q = j & 3;
            uint32_t d = (uint32_t)(n * RSTRB + q * 16);
            cp16(base + OFF_BH + d, Wth + (size_t)(nBase + n) * KTOT + ko + q * 8);
            cp16(base + OFF_BL + d, Wtl + (size_t)(nBase + n) * KTOT + ko + q * 8);
        }
    };
    auto stsA = [&](int buf) {
        const uint32_t base = sb + buf * STAGE;
        #pragma unroll
        for (int u = 0; u < 4; ++u) {
            int j = tid + 256 * u;
            int r = j >> 3, c = j & 7;
            uint32_t h0, l0, h1, l1;
            splitbf2(avr[u].x, avr[u].y, h0, l0);
            splitbf2(avr[u].z, avr[u].w, h1, l1);
            uint32_t d = (uint32_t)(r * RSTRB + c * 8);
            sts64(base + d, h0, h1);
            sts64(base + OFF_AL + d, l0, l1);
        }
    };

    // prologue
    cpB(0, 0);
    asm volatile("cp.async.commit_group;" ::: "memory");
    ldgA(0);
    stsA(0);
    asm volatile("cp.async.wait_group 0;" ::: "memory");
    __syncthreads();

    for (int it = 0; it < NIT; ++it) {
        const int cur = it & 1, nxt = cur ^ 1;
        const bool more = (it + 1) < NIT;
        if (more) {
            cpB(it + 1, nxt);
            asm volatile("cp.async.commit_group;" ::: "memory");
            ldgA(it + 1);
        }

        const uint32_t st = sb + cur * STAGE;
        #pragma unroll
        for (int ks = 0; ks < 2; ++ks) {
            uint32_t ah[2][4], al_[2][4];
            #pragma unroll
            for (int mt = 0; mt < 2; ++mt) {
                uint32_t ao = st + a_off + mt * (16 * RSTRB) + ks * 32;
                ldsm4(ah[mt], ao);
                ldsm4(al_[mt], ao + OFF_AL);
            }
            #pragma unroll
            for (int p = 0; p < 4; ++p) {
                uint32_t bh[4], bl[4];
                uint32_t bo = st + OFF_BH + b_off + p * (16 * RSTRB) + ks * 32;
                ldsm4(bh, bo);
                ldsm4(bl, bo + TILEB);
                #pragma unroll
                for (int mt = 0; mt < 2; ++mt)
                    #pragma unroll
                    for (int q = 0; q < 2; ++q)
                        mma_bf16(acc[mt][p * 2 + q], ah[mt], &bh[q * 2]);
                #pragma unroll
                for (int mt = 0; mt < 2; ++mt)
                    #pragma unroll
                    for (int q = 0; q < 2; ++q)
                        mma_bf16(acc[mt][p * 2 + q], ah[mt], &bl[q * 2]);
                #pragma unroll
                for (int mt = 0; mt < 2; ++mt)
                    #pragma unroll
                    for (int q = 0; q < 2; ++q)
                        mma_bf16(acc[mt][p * 2 + q], al_[mt], &bh[q * 2]);
            }
        }

        if (more) stsA(nxt);
        asm volatile("cp.async.wait_group 0;" ::: "memory");
        __syncthreads();
    }

    // epilogue: + w @ bias, activation, store
    #pragma unroll
    for (int mt = 0; mt < 2; ++mt) {
        const int r0 = wm * 32 + mt * 16 + g;
        float w0[8], w1[8];
        #pragma unroll
        for (int e = 0; e < 8; ++e) {
            w0[e] = wsm[r0 * 8 + e];
            w1[e] = wsm[(r0 + 8) * 8 + e];
        }
        #pragma unroll
        for (int nf = 0; nf < 8; ++nf) {
            const int c = wn * 64 + nf * 8 + t * 2;
            float b00 = 0.f, b01 = 0.f, b10 = 0.f, b11 = 0.f;
            #pragma unroll
            for (int e = 0; e < 8; ++e) {
                float be0 = bsm[e * 128 + c], be1 = bsm[e * 128 + c + 1];
                b00 = fmaf(w0[e], be0, b00); b01 = fmaf(w0[e], be1, b01);
                b10 = fmaf(w1[e], be0, b10); b11 = fmaf(w1[e], be1, b11);
            }
            float v0 = acc[mt][nf][0] + b00;
            float v1 = acc[mt][nf][1] + b01;
            float v2 = acc[mt][nf][2] + b10;
            float v3 = acc[mt][nf][3] + b11;
            if (ACT) { v0 = eluf(v0); v1 = eluf(v1); v2 = eluf(v2); v3 = eluf(v3); }
            *(float2*)(Y + (size_t)(mBase + r0)     * DH + nBase + c) = make_float2(v0, v1);
            *(float2*)(Y + (size_t)(mBase + r0 + 8) * DH + nBase + c) = make_float2(v2, v3);
        }
    }
}

// ---------------------------------------------------------------------------
extern "C" void kernel_launch(void* const* d_in, const int* in_sizes, int n_in,
                              void* d_out, int out_size)
{
    const float* z   = (const float*)d_in[0];
    const void*  idx = (const void*)d_in[1];
    const float* Wg1 = (const float*)d_in[2];
    const float* bg1 = (const float*)d_in[3];
    const float* Wg2 = (const float*)d_in[4];
    const float* bg2 = (const float*)d_in[5];
    const float* Wg3 = (const float*)d_in[6];
    const float* bg3 = (const float*)d_in[7];
    const float* W1  = (const float*)d_in[8];
    const float* b1  = (const float*)d_in[9];
    const float* W2  = (const float*)d_in[10];
    const float* b2  = (const float*)d_in[11];
    const float* W3  = (const float*)d_in[12];
    const float* b3  = (const float*)d_in[13];
    float* out = (float*)d_out;

    cudaFuncSetAttribute(layer_mm<true , 0>, cudaFuncAttributeMaxDynamicSharedMemorySize, SMEM_BYTES);
    cudaFuncSetAttribute(layer_mm<true , 1>, cudaFuncAttributeMaxDynamicSharedMemorySize, SMEM_BYTES);
    cudaFuncSetAttribute(layer_mm<false, 2>, cudaFuncAttributeMaxDynamicSharedMemorySize, SMEM_BYTES);

    gating_kernel<<<1024, 256>>>(z, idx, Wg1, bg1, Wg2, bg2, Wg3, bg3);

    dim3 wgrid(KTOT / 32, DH / 32);   // (128, 16)
    dim3 wblk(32, 8);
    wsplit_kernel<<<wgrid, wblk>>>(W1, 0);
    wsplit_kernel<<<wgrid, wblk>>>(W2, 1);
    wsplit_kernel<<<wgrid, wblk>>>(W3, 2);

    dim3 grid(DH / BN, BATCH / BM);   // (4, 512)
    layer_mm<true , 0><<<grid, 256, SMEM_BYTES>>>(z, b1, nullptr);
    layer_mm<true , 1><<<grid, 256, SMEM_BYTES>>>(nullptr, b2, nullptr);
    layer_mm<false, 2><<<grid, 256, SMEM_BYTES>>>(nullptr, b3, out);
}